// round 11
// baseline (speedup 1.0000x reference)
#include <cuda_runtime.h>
#include <math.h>
#include <stdint.h>

// Problem constants
#define BB 8
#define TT 1024
#define CC 768
#define NHH 12
#define HDD 64

// Scratch (static __device__ arrays: no allocation allowed)
__device__ float g_v  [BB * TT * CC];   // value projection [B,T,C]
__device__ float g_u  [BB * TT * CC];   // u = Wcl @ v  [B,T,C]
__device__ float g_wcl[TT * TT];        // Wc @ Wl
__device__ float g_y  [BB * TT * CC];   // attention output [B,T,C]

// ===========================================================================
// tf32 helpers (base sm_80+ ISA — harness compiles compute_103, no tcgen05)
// ===========================================================================
__device__ __forceinline__ float f2tf32f(float x) {
    uint32_t u;
    asm("cvt.rna.tf32.f32 %0, %1;" : "=r"(u) : "f"(x));
    return __uint_as_float(u);
}

__device__ __forceinline__ void mma_tf32_16x8x8(
    float* d, const float4& a, const float2& b)
{
    asm volatile(
        "mma.sync.aligned.m16n8k8.row.col.f32.tf32.tf32.f32 "
        "{%0,%1,%2,%3}, {%4,%5,%6,%7}, {%8,%9}, {%0,%1,%2,%3};"
        : "+f"(d[0]), "+f"(d[1]), "+f"(d[2]), "+f"(d[3])
        : "r"(__float_as_uint(a.x)), "r"(__float_as_uint(a.y)),
          "r"(__float_as_uint(a.z)), "r"(__float_as_uint(a.w)),
          "r"(__float_as_uint(b.x)), "r"(__float_as_uint(b.y)));
}

// ===========================================================================
// Generic batched tf32 mma.sync GEMM (engine unchanged; used for steps 1,2,3,7)
// ===========================================================================
template<int BN, int WM, int WN, bool TB, bool SKIP_OUT, bool SKIP_K>
__global__ void __launch_bounds__(256)
gemm_mma_k(const float* __restrict__ A, const float* __restrict__ Bm,
           const float* __restrict__ bias, float* __restrict__ Cm,
           int K, int lda, int ldb, int ldc,
           long long sAb, long long sAh, long long sBb, long long sBh,
           long long sCb, long long sCh, int batchH, float alpha)
{
    constexpr int BM = 128, BK = 32;
    constexpr int MA = BM / WM / 16;
    constexpr int NA = BN / WN / 8;
    static_assert(WM * WN == 8, "8 warps");

    const int nt = blockIdx.x, mt = blockIdx.y;
    if (SKIP_OUT && nt > mt) return;
    const int z = blockIdx.z;
    const int b = z / batchH, h = z % batchH;
    const float* Az = A + b * sAb + h * sAh + (long long)mt * BM * lda;
    const float* Bz = Bm + b * sBb + h * sBh
                    + (TB ? (long long)nt * BN * ldb : (long long)nt * BN);
    float* Cz = Cm + b * sCb + h * sCh;

    __shared__ float sA[4][8][32][4];
    __shared__ float sB[4][BN / 8][32][2];

    const int tid = threadIdx.x, lane = tid & 31, w = tid >> 5;
    const int wm = w / WN, wn = w % WN;

    float acc[MA][NA][4];
#pragma unroll
    for (int i = 0; i < MA; i++)
#pragma unroll
        for (int j = 0; j < NA; j++)
#pragma unroll
            for (int r = 0; r < 4; r++) acc[i][j][r] = 0.f;

    const int kmax = SKIP_K ? (mt + 1) * BM : K;

    for (int k0 = 0; k0 < kmax; k0 += BK) {
#pragma unroll
        for (int i = 0; i < 4; i++) {
            int v = tid + i * 256;
            int row = v >> 3, c4 = v & 7;
            int ka = c4 >> 1;
            int r = (c4 & 1) * 2 + ((row >> 3) & 1);
            int ma = row >> 4, laneA = (row & 7) * 4;
            float4 t = *reinterpret_cast<const float4*>(
                &Az[(long long)row * lda + k0 + c4 * 4]);
            sA[ka][ma][laneA + 0][r] = f2tf32f(t.x);
            sA[ka][ma][laneA + 1][r] = f2tf32f(t.y);
            sA[ka][ma][laneA + 2][r] = f2tf32f(t.z);
            sA[ka][ma][laneA + 3][r] = f2tf32f(t.w);
        }
        if constexpr (TB) {
#pragma unroll
            for (int i = 0; i < BN / 32; i++) {
                int v = tid + i * 256;
                int n = v >> 3, c4 = v & 7;
                int ka = c4 >> 1, r = c4 & 1;
                int na = n >> 3, laneB = (n & 7) * 4;
                float4 t = *reinterpret_cast<const float4*>(
                    &Bz[(long long)n * ldb + k0 + c4 * 4]);
                sB[ka][na][laneB + 0][r] = f2tf32f(t.x);
                sB[ka][na][laneB + 1][r] = f2tf32f(t.y);
                sB[ka][na][laneB + 2][r] = f2tf32f(t.z);
                sB[ka][na][laneB + 3][r] = f2tf32f(t.w);
            }
        } else {
#pragma unroll
            for (int i = 0; i < BN / 32; i++) {
                int v = tid + i * 256;
                int krow = v / (BN / 4);
                int nc = (v % (BN / 4)) * 4;
                int ka = krow >> 3, kc = krow & 7;
                int r = kc >> 2, lc = kc & 3;
                int na = nc >> 3, nb = nc & 7;
                float4 t = *reinterpret_cast<const float4*>(
                    &Bz[(long long)(k0 + krow) * ldb + nc]);
                sB[ka][na][(nb + 0) * 4 + lc][r] = f2tf32f(t.x);
                sB[ka][na][(nb + 1) * 4 + lc][r] = f2tf32f(t.y);
                sB[ka][na][(nb + 2) * 4 + lc][r] = f2tf32f(t.z);
                sB[ka][na][(nb + 3) * 4 + lc][r] = f2tf32f(t.w);
            }
        }
        __syncthreads();

#pragma unroll
        for (int ka = 0; ka < 4; ka++) {
            float4 aF[MA];
            float2 bF[NA];
#pragma unroll
            for (int i = 0; i < MA; i++)
                aF[i] = *reinterpret_cast<const float4*>(&sA[ka][wm * MA + i][lane][0]);
#pragma unroll
            for (int j = 0; j < NA; j++)
                bF[j] = *reinterpret_cast<const float2*>(&sB[ka][wn * NA + j][lane][0]);
#pragma unroll
            for (int i = 0; i < MA; i++)
#pragma unroll
                for (int j = 0; j < NA; j++)
                    mma_tf32_16x8x8(acc[i][j], aF[i], bF[j]);
        }
        __syncthreads();
    }

    const int m_base = mt * BM + wm * (MA * 16);
    const int n_base = nt * BN + wn * (NA * 8);
#pragma unroll
    for (int i = 0; i < MA; i++) {
        int row0 = m_base + i * 16 + (lane >> 2);
#pragma unroll
        for (int j = 0; j < NA; j++) {
            int col = n_base + j * 8 + (lane & 3) * 2;
            float b0 = bias ? bias[col] : 0.f;
            float b1 = bias ? bias[col + 1] : 0.f;
            float2 t0 = make_float2(acc[i][j][0] * alpha + b0,
                                    acc[i][j][1] * alpha + b1);
            float2 t1 = make_float2(acc[i][j][2] * alpha + b0,
                                    acc[i][j][3] * alpha + b1);
            *reinterpret_cast<float2*>(&Cz[(long long)row0 * ldc + col]) = t0;
            *reinterpret_cast<float2*>(&Cz[(long long)(row0 + 8) * ldc + col]) = t1;
        }
    }
}

// ===========================================================================
// Flash kernel (steps 4+5+6). R11: sP eliminated via in-register C->A
// fragment transpose (8 shuffles + 4 selects per 16x8 atom).
// smem: sQ 32K | sU 32K | sV 32K | sBc 4K = 100 KB -> 2 CTAs/SM.
// 8 warps, WM=8/WN=1 in both MMA phases; softmax stats quad-local.
// ===========================================================================
#define FLASH_SMEM_FLOATS 25600   // 8192+8192+8192+1024
#define FLASH_SMEM_BYTES  (FLASH_SMEM_FLOATS * 4)

__global__ void __launch_bounds__(256)
flash_attn_k(const float* __restrict__ vv, const float* __restrict__ uu,
             const float* __restrict__ bc, float* __restrict__ yy)
{
    const int mt = 7 - blockIdx.x;          // heavy tiles first
    const int z = blockIdx.y;
    const int b = z / NHH, h = z % NHH;

    const float* Qg = vv + ((long long)(b * TT + mt * 128)) * CC + h * HDD;
    const float* Ub = uu + (long long)b * TT * CC + h * HDD;
    const float* Vb = vv + (long long)b * TT * CC + h * HDD;
    float* Cz = yy + (long long)b * TT * CC + h * HDD;

    extern __shared__ float sm[];
    float* sQ  = sm;            // [ka8][ma8][lane32][r4]
    float* sU  = sm + 8192;     // [ka8][na16][lane32][r2]
    float* sV  = sm + 16384;    // [ka16][na8][lane32][r2]
    float* sBc = sm + 24576;    // [1024]

    const int tid = threadIdx.x, lane = tid & 31, w = tid >> 5;
    const int g = lane >> 2, lq = lane & 3;

    // ---- load q tile (128 x 64) into A-frag layout; bc row ----
#pragma unroll
    for (int i = 0; i < 8; i++) {
        int v = tid + i * 256;
        int row = v >> 4, c4 = v & 15;
        int ka = c4 >> 1;
        int r = (c4 & 1) * 2 + ((row >> 3) & 1);
        int base = ((ka * 8 + (row >> 4)) * 32 + (row & 7) * 4) * 4 + r;
        float4 t = *reinterpret_cast<const float4*>(&Qg[(long long)row * CC + c4 * 4]);
        sQ[base + 0 * 4] = f2tf32f(t.x);
        sQ[base + 1 * 4] = f2tf32f(t.y);
        sQ[base + 2 * 4] = f2tf32f(t.z);
        sQ[base + 3 * 4] = f2tf32f(t.w);
    }
    for (int i = tid; i < TT; i += 256) sBc[i] = bc[i];

    float yacc[8][4];
    float mrun0 = -INFINITY, mrun1 = -INFINITY, lrun0 = 0.f, lrun1 = 0.f;
#pragma unroll
    for (int j = 0; j < 8; j++)
#pragma unroll
        for (int r = 0; r < 4; r++) yacc[j][r] = 0.f;

    // shuffle-transpose source lanes (C-frag -> A-frag)
    const int srcA = (lane & 28) | (lq >> 1);
    const int srcB = srcA + 2;
    const bool oddq = (lq & 1);

    __syncthreads();

    for (int jt = 0; jt <= mt; jt++) {
        const float* Uj = Ub + (long long)(jt * 128) * CC;
        const float* Vj = Vb + (long long)(jt * 128) * CC;
        // ---- load u_j tile (128n x 64k) B-frag (TB) ----
#pragma unroll
        for (int i = 0; i < 8; i++) {
            int v = tid + i * 256;
            int n = v >> 4, c4 = v & 15;
            int ka = c4 >> 1, r = c4 & 1;
            int base = ((ka * 16 + (n >> 3)) * 32 + (n & 7) * 4) * 2 + r;
            float4 t = *reinterpret_cast<const float4*>(&Uj[(long long)n * CC + c4 * 4]);
            sU[base + 0 * 2] = f2tf32f(t.x);
            sU[base + 1 * 2] = f2tf32f(t.y);
            sU[base + 2 * 2] = f2tf32f(t.z);
            sU[base + 3 * 2] = f2tf32f(t.w);
        }
        // ---- load v_j tile (128k x 64n) B-frag (NN) ----
#pragma unroll
        for (int i = 0; i < 8; i++) {
            int v = tid + i * 256;
            int krow = v >> 4;
            int nc = (v & 15) * 4;
            int ka = krow >> 3, kc = krow & 7;
            int r = kc >> 2, lc = kc & 3;
            int na = nc >> 3, nb = nc & 7;
            float4 t = *reinterpret_cast<const float4*>(&Vj[(long long)krow * CC + nc]);
            sV[((ka * 8 + na) * 32 + (nb + 0) * 4 + lc) * 2 + r] = f2tf32f(t.x);
            sV[((ka * 8 + na) * 32 + (nb + 1) * 4 + lc) * 2 + r] = f2tf32f(t.y);
            sV[((ka * 8 + na) * 32 + (nb + 2) * 4 + lc) * 2 + r] = f2tf32f(t.z);
            sV[((ka * 8 + na) * 32 + (nb + 3) * 4 + lc) * 2 + r] = f2tf32f(t.w);
        }
        __syncthreads();

        // ---- phase A: S = q @ u_j^T  (warp w: rows w*16..+15, 128 cols) ----
        float sAcc[16][4];
#pragma unroll
        for (int na = 0; na < 16; na++)
#pragma unroll
            for (int r = 0; r < 4; r++) sAcc[na][r] = 0.f;
#pragma unroll
        for (int ka = 0; ka < 8; ka++) {
            float4 aF = *reinterpret_cast<const float4*>(&sQ[((ka * 8 + w) * 32 + lane) * 4]);
#pragma unroll
            for (int na = 0; na < 16; na++) {
                float2 bF = *reinterpret_cast<const float2*>(&sU[((ka * 16 + na) * 32 + lane) * 2]);
                mma_tf32_16x8x8(sAcc[na], aF, bF);
            }
        }

        // ---- phase B: scale+bias, mask, tile max, rescale ----
        const bool diag = (jt == mt);
        const int r0 = w * 16 + g;
        float tm0 = -INFINITY, tm1 = -INFINITY;
#pragma unroll
        for (int na = 0; na < 16; na++) {
            int c0 = na * 8 + 2 * lq;
            float2 bb = *reinterpret_cast<const float2*>(&sBc[jt * 128 + c0]);
            float s0 = sAcc[na][0] * 0.125f + bb.x;
            float s1 = sAcc[na][1] * 0.125f + bb.y;
            float s2 = sAcc[na][2] * 0.125f + bb.x;
            float s3 = sAcc[na][3] * 0.125f + bb.y;
            if (diag) {
                if (c0 > r0)         s0 = -1e30f;
                if (c0 + 1 > r0)     s1 = -1e30f;
                if (c0 > r0 + 8)     s2 = -1e30f;
                if (c0 + 1 > r0 + 8) s3 = -1e30f;
            }
            sAcc[na][0] = s0; sAcc[na][1] = s1; sAcc[na][2] = s2; sAcc[na][3] = s3;
            tm0 = fmaxf(tm0, fmaxf(s0, s1));
            tm1 = fmaxf(tm1, fmaxf(s2, s3));
        }
        tm0 = fmaxf(tm0, __shfl_xor_sync(0xffffffffu, tm0, 1));
        tm0 = fmaxf(tm0, __shfl_xor_sync(0xffffffffu, tm0, 2));
        tm1 = fmaxf(tm1, __shfl_xor_sync(0xffffffffu, tm1, 1));
        tm1 = fmaxf(tm1, __shfl_xor_sync(0xffffffffu, tm1, 2));

        const float nm0 = fmaxf(mrun0, tm0);
        const float nm1 = fmaxf(mrun1, tm1);
        const float sc0 = __expf(mrun0 - nm0);
        const float sc1 = __expf(mrun1 - nm1);
        mrun0 = nm0; mrun1 = nm1;
        lrun0 *= sc0; lrun1 *= sc1;
#pragma unroll
        for (int j = 0; j < 8; j++) {
            yacc[j][0] *= sc0; yacc[j][1] *= sc0;
            yacc[j][2] *= sc1; yacc[j][3] *= sc1;
        }

        // ---- phase B2+C fused per k-atom: exp -> shuffle-transpose -> MMA ----
        float ts0 = 0.f, ts1 = 0.f;
#pragma unroll
        for (int na = 0; na < 16; na++) {
            float p0 = __expf(sAcc[na][0] - nm0);
            float p1 = __expf(sAcc[na][1] - nm0);
            float p2 = __expf(sAcc[na][2] - nm1);
            float p3 = __expf(sAcc[na][3] - nm1);
            ts0 += p0 + p1;
            ts1 += p2 + p3;
            // C-frag (g,2lq)/(g,2lq+1)/(g+8,..) -> A-frag (g,lq)/(g+8,lq)/(g,lq+4)/(g+8,lq+4)
            float e0A = __shfl_sync(0xffffffffu, p0, srcA);
            float e1A = __shfl_sync(0xffffffffu, p1, srcA);
            float e2A = __shfl_sync(0xffffffffu, p2, srcA);
            float e3A = __shfl_sync(0xffffffffu, p3, srcA);
            float e0B = __shfl_sync(0xffffffffu, p0, srcB);
            float e1B = __shfl_sync(0xffffffffu, p1, srcB);
            float e2B = __shfl_sync(0xffffffffu, p2, srcB);
            float e3B = __shfl_sync(0xffffffffu, p3, srcB);
            float4 aP;
            aP.x = f2tf32f(oddq ? e1A : e0A);   // (g, lq)
            aP.y = f2tf32f(oddq ? e3A : e2A);   // (g+8, lq)
            aP.z = f2tf32f(oddq ? e1B : e0B);   // (g, lq+4)
            aP.w = f2tf32f(oddq ? e3B : e2B);   // (g+8, lq+4)
#pragma unroll
            for (int j = 0; j < 8; j++) {
                float2 bF = *reinterpret_cast<const float2*>(&sV[((na * 8 + j) * 32 + lane) * 2]);
                mma_tf32_16x8x8(yacc[j], aP, bF);
            }
        }
        ts0 += __shfl_xor_sync(0xffffffffu, ts0, 1);
        ts0 += __shfl_xor_sync(0xffffffffu, ts0, 2);
        ts1 += __shfl_xor_sync(0xffffffffu, ts1, 1);
        ts1 += __shfl_xor_sync(0xffffffffu, ts1, 2);
        lrun0 += ts0; lrun1 += ts1;

        __syncthreads();   // before next iteration overwrites sU/sV
    }

    // ---- epilogue: normalize, store ----
    const int row0 = mt * 128 + w * 16 + g;
    const float inv0 = 1.f / lrun0;
    const float inv1 = 1.f / lrun1;
#pragma unroll
    for (int j = 0; j < 8; j++) {
        int col = j * 8 + lq * 2;
        float2 t0 = make_float2(yacc[j][0] * inv0, yacc[j][1] * inv0);
        float2 t1 = make_float2(yacc[j][2] * inv1, yacc[j][3] * inv1);
        *reinterpret_cast<float2*>(&Cz[(long long)row0 * CC + col]) = t0;
        *reinterpret_cast<float2*>(&Cz[(long long)(row0 + 8) * CC + col]) = t1;
    }
}

// ---------------------------------------------------------------------------
extern "C" void kernel_launch(void* const* d_in, const int* in_sizes, int n_in,
                              void* d_out, int out_size)
{
    const float* x  = (const float*)d_in[0];
    const float* Wv = (const float*)d_in[1];
    const float* bv = (const float*)d_in[2];
    const float* Wl = (const float*)d_in[3];
    const float* Wc = (const float*)d_in[4];
    const float* bc = (const float*)d_in[5];
    const float* Wp = (const float*)d_in[6];
    const float* bp = (const float*)d_in[7];
    float* out = (float*)d_out;

    float *v_p, *u_p, *wcl_p, *y_p;
    cudaGetSymbolAddress((void**)&v_p,   g_v);
    cudaGetSymbolAddress((void**)&u_p,   g_u);
    cudaGetSymbolAddress((void**)&wcl_p, g_wcl);
    cudaGetSymbolAddress((void**)&y_p,   g_y);

    const long long sBTC = (long long)TT * CC;

    cudaFuncSetAttribute(flash_attn_k,
                         cudaFuncAttributeMaxDynamicSharedMemorySize,
                         FLASH_SMEM_BYTES);

    // 1) Wcl = Wc @ Wl   (tf32 NN)
    gemm_mma_k<128,2,4,false,false,false><<<dim3(8,8,1),256>>>(
        Wc, Wl, nullptr, wcl_p,
        TT, TT, TT, TT,
        0,0, 0,0, 0,0, 1, 1.0f);

    // 2) v = x @ Wv^T + bv   (tf32 NT)
    gemm_mma_k<128,2,4,true,false,false><<<dim3(CC/128, (BB*TT)/128, 1),256>>>(
        x, Wv, bv, v_p,
        CC, CC, CC, CC,
        0,0, 0,0, 0,0, 1, 1.0f);

    // 3) u[b] = Wcl @ v[b]   (tf32 NN, head-merged N=768)
    gemm_mma_k<128,2,4,false,false,false><<<dim3(CC/128, 8, BB),256>>>(
        wcl_p, v_p, nullptr, u_p,
        TT, TT, CC, CC,
        0,0, sBTC,0, sBTC,0, 1, 1.0f);

    // 4+5+6) y = softmax_causal(vh @ uh^T/8 + bc) @ vh   — fused flash
    flash_attn_k<<<dim3(8, BB*NHH), 256, FLASH_SMEM_BYTES>>>(
        v_p, u_p, bc, y_p);

    // 7) out = y @ Wp^T + bp   (tf32 NT)
    gemm_mma_k<128,2,4,true,false,false><<<dim3(CC/128, (BB*TT)/128, 1),256>>>(
        y_p, Wp, bp, out,
        CC, CC, CC, CC,
        0,0, 0,0, 0,0, 1, 1.0f);
}

// round 14
// speedup vs baseline: 1.0550x; 1.0550x over previous
#include <cuda_runtime.h>
#include <math.h>
#include <stdint.h>

// Problem constants
#define BB 8
#define TT 1024
#define CC 768
#define NHH 12
#define HDD 64

// Scratch (static __device__ arrays: no allocation allowed)
__device__ float g_v  [BB * TT * CC];   // value projection [B,T,C]
__device__ float g_u  [BB * TT * CC];   // u = Wcl @ v  [B,T,C]
__device__ float g_wcl[TT * TT];        // Wc @ Wl
__device__ float g_y  [BB * TT * CC];   // attention output [B,T,C]

// ===========================================================================
// tf32 helpers (base sm_80+ ISA — harness compiles compute_103, no tcgen05)
// ===========================================================================
__device__ __forceinline__ float f2tf32f(float x) {
    uint32_t u;
    asm("cvt.rna.tf32.f32 %0, %1;" : "=r"(u) : "f"(x));
    return __uint_as_float(u);
}

__device__ __forceinline__ void mma_tf32_16x8x8(
    float* d, const float4& a, const float2& b)
{
    asm volatile(
        "mma.sync.aligned.m16n8k8.row.col.f32.tf32.tf32.f32 "
        "{%0,%1,%2,%3}, {%4,%5,%6,%7}, {%8,%9}, {%0,%1,%2,%3};"
        : "+f"(d[0]), "+f"(d[1]), "+f"(d[2]), "+f"(d[3])
        : "r"(__float_as_uint(a.x)), "r"(__float_as_uint(a.y)),
          "r"(__float_as_uint(a.z)), "r"(__float_as_uint(a.w)),
          "r"(__float_as_uint(b.x)), "r"(__float_as_uint(b.y)));
}

// ===========================================================================
// Generic batched tf32 mma.sync GEMM (engine unchanged; used for steps 1,2,3,7)
// ===========================================================================
template<int BN, int WM, int WN, bool TB, bool SKIP_OUT, bool SKIP_K>
__global__ void __launch_bounds__(256)
gemm_mma_k(const float* __restrict__ A, const float* __restrict__ Bm,
           const float* __restrict__ bias, float* __restrict__ Cm,
           int K, int lda, int ldb, int ldc,
           long long sAb, long long sAh, long long sBb, long long sBh,
           long long sCb, long long sCh, int batchH, float alpha)
{
    constexpr int BM = 128, BK = 32;
    constexpr int MA = BM / WM / 16;
    constexpr int NA = BN / WN / 8;
    static_assert(WM * WN == 8, "8 warps");

    const int nt = blockIdx.x, mt = blockIdx.y;
    if (SKIP_OUT && nt > mt) return;
    const int z = blockIdx.z;
    const int b = z / batchH, h = z % batchH;
    const float* Az = A + b * sAb + h * sAh + (long long)mt * BM * lda;
    const float* Bz = Bm + b * sBb + h * sBh
                    + (TB ? (long long)nt * BN * ldb : (long long)nt * BN);
    float* Cz = Cm + b * sCb + h * sCh;

    __shared__ float sA[4][8][32][4];
    __shared__ float sB[4][BN / 8][32][2];

    const int tid = threadIdx.x, lane = tid & 31, w = tid >> 5;
    const int wm = w / WN, wn = w % WN;

    float acc[MA][NA][4];
#pragma unroll
    for (int i = 0; i < MA; i++)
#pragma unroll
        for (int j = 0; j < NA; j++)
#pragma unroll
            for (int r = 0; r < 4; r++) acc[i][j][r] = 0.f;

    const int kmax = SKIP_K ? (mt + 1) * BM : K;

    for (int k0 = 0; k0 < kmax; k0 += BK) {
#pragma unroll
        for (int i = 0; i < 4; i++) {
            int v = tid + i * 256;
            int row = v >> 3, c4 = v & 7;
            int ka = c4 >> 1;
            int r = (c4 & 1) * 2 + ((row >> 3) & 1);
            int ma = row >> 4, laneA = (row & 7) * 4;
            float4 t = *reinterpret_cast<const float4*>(
                &Az[(long long)row * lda + k0 + c4 * 4]);
            sA[ka][ma][laneA + 0][r] = f2tf32f(t.x);
            sA[ka][ma][laneA + 1][r] = f2tf32f(t.y);
            sA[ka][ma][laneA + 2][r] = f2tf32f(t.z);
            sA[ka][ma][laneA + 3][r] = f2tf32f(t.w);
        }
        if constexpr (TB) {
#pragma unroll
            for (int i = 0; i < BN / 32; i++) {
                int v = tid + i * 256;
                int n = v >> 3, c4 = v & 7;
                int ka = c4 >> 1, r = c4 & 1;
                int na = n >> 3, laneB = (n & 7) * 4;
                float4 t = *reinterpret_cast<const float4*>(
                    &Bz[(long long)n * ldb + k0 + c4 * 4]);
                sB[ka][na][laneB + 0][r] = f2tf32f(t.x);
                sB[ka][na][laneB + 1][r] = f2tf32f(t.y);
                sB[ka][na][laneB + 2][r] = f2tf32f(t.z);
                sB[ka][na][laneB + 3][r] = f2tf32f(t.w);
            }
        } else {
#pragma unroll
            for (int i = 0; i < BN / 32; i++) {
                int v = tid + i * 256;
                int krow = v / (BN / 4);
                int nc = (v % (BN / 4)) * 4;
                int ka = krow >> 3, kc = krow & 7;
                int r = kc >> 2, lc = kc & 3;
                int na = nc >> 3, nb = nc & 7;
                float4 t = *reinterpret_cast<const float4*>(
                    &Bz[(long long)(k0 + krow) * ldb + nc]);
                sB[ka][na][(nb + 0) * 4 + lc][r] = f2tf32f(t.x);
                sB[ka][na][(nb + 1) * 4 + lc][r] = f2tf32f(t.y);
                sB[ka][na][(nb + 2) * 4 + lc][r] = f2tf32f(t.z);
                sB[ka][na][(nb + 3) * 4 + lc][r] = f2tf32f(t.w);
            }
        }
        __syncthreads();

#pragma unroll
        for (int ka = 0; ka < 4; ka++) {
            float4 aF[MA];
            float2 bF[NA];
#pragma unroll
            for (int i = 0; i < MA; i++)
                aF[i] = *reinterpret_cast<const float4*>(&sA[ka][wm * MA + i][lane][0]);
#pragma unroll
            for (int j = 0; j < NA; j++)
                bF[j] = *reinterpret_cast<const float2*>(&sB[ka][wn * NA + j][lane][0]);
#pragma unroll
            for (int i = 0; i < MA; i++)
#pragma unroll
                for (int j = 0; j < NA; j++)
                    mma_tf32_16x8x8(acc[i][j], aF[i], bF[j]);
        }
        __syncthreads();
    }

    const int m_base = mt * BM + wm * (MA * 16);
    const int n_base = nt * BN + wn * (NA * 8);
#pragma unroll
    for (int i = 0; i < MA; i++) {
        int row0 = m_base + i * 16 + (lane >> 2);
#pragma unroll
        for (int j = 0; j < NA; j++) {
            int col = n_base + j * 8 + (lane & 3) * 2;
            float b0 = bias ? bias[col] : 0.f;
            float b1 = bias ? bias[col + 1] : 0.f;
            float2 t0 = make_float2(acc[i][j][0] * alpha + b0,
                                    acc[i][j][1] * alpha + b1);
            float2 t1 = make_float2(acc[i][j][2] * alpha + b0,
                                    acc[i][j][3] * alpha + b1);
            *reinterpret_cast<float2*>(&Cz[(long long)row0 * ldc + col]) = t0;
            *reinterpret_cast<float2*>(&Cz[(long long)(row0 + 8) * ldc + col]) = t1;
        }
    }
}

// ===========================================================================
// Flash kernel (steps 4+5+6), R12: 64-wide key chunks.
//   sAcc 8 atoms (32 regs) + yacc 32 regs -> fits 128-reg budget;
//   __launch_bounds__(256,2) enforces 2 CTAs/SM.
// smem: sQ 32K | sU 16K | sV 16K | sBc 4K = 68 KB.
// 8 warps, warp w owns rows w*16..w*16+15; softmax stats quad-local;
// in-register C->A fragment transpose (no sP).
// Warp-level skip of fully-masked diagonal chunks.
// ===========================================================================
#define FLASH_SMEM_FLOATS 17408   // 8192 + 4096 + 4096 + 1024
#define FLASH_SMEM_BYTES  (FLASH_SMEM_FLOATS * 4)

__global__ void __launch_bounds__(256, 2)
flash_attn_k(const float* __restrict__ vv, const float* __restrict__ uu,
             const float* __restrict__ bc, float* __restrict__ yy)
{
    const int mt = 7 - blockIdx.x;          // heavy tiles first
    const int z = blockIdx.y;
    const int b = z / NHH, h = z % NHH;

    const float* Qg = vv + ((long long)(b * TT + mt * 128)) * CC + h * HDD;
    const float* Ub = uu + (long long)b * TT * CC + h * HDD;
    const float* Vb = vv + (long long)b * TT * CC + h * HDD;
    float* Cz = yy + (long long)b * TT * CC + h * HDD;

    extern __shared__ float sm[];
    float* sQ  = sm;            // [ka8][ma8][lane32][r4]   (32 KB)
    float* sU  = sm + 8192;     // [ka8][na8][lane32][r2]   (16 KB)
    float* sV  = sm + 12288;    // [ka8][na8][lane32][r2]   (16 KB)
    float* sBc = sm + 16384;    // [1024]

    const int tid = threadIdx.x, lane = tid & 31, w = tid >> 5;
    const int g = lane >> 2, lq = lane & 3;

    // ---- load q tile (128 x 64) into A-frag layout; bc ----
#pragma unroll
    for (int i = 0; i < 8; i++) {
        int v = tid + i * 256;
        int row = v >> 4, c4 = v & 15;
        int ka = c4 >> 1;
        int r = (c4 & 1) * 2 + ((row >> 3) & 1);
        int base = ((ka * 8 + (row >> 4)) * 32 + (row & 7) * 4) * 4 + r;
        float4 t = *reinterpret_cast<const float4*>(&Qg[(long long)row * CC + c4 * 4]);
        sQ[base + 0 * 4] = f2tf32f(t.x);
        sQ[base + 1 * 4] = f2tf32f(t.y);
        sQ[base + 2 * 4] = f2tf32f(t.z);
        sQ[base + 3 * 4] = f2tf32f(t.w);
    }
    for (int i = tid; i < TT; i += 256) sBc[i] = bc[i];

    float yacc[8][4];
    float mrun0 = -INFINITY, mrun1 = -INFINITY, lrun0 = 0.f, lrun1 = 0.f;
#pragma unroll
    for (int j = 0; j < 8; j++)
#pragma unroll
        for (int r = 0; r < 4; r++) yacc[j][r] = 0.f;

    // shuffle-transpose source lanes (C-frag -> A-frag)
    const int srcA = (lane & 28) | (lq >> 1);
    const int srcB = srcA + 2;
    const bool oddq = (lq & 1);

    const int r0g = mt * 128 + w * 16 + g;     // global row of a0 for this thread
    const int rmaxw = mt * 128 + w * 16 + 15;  // warp's max row

    __syncthreads();

    const int nchunks = 2 * (mt + 1);
    for (int jc = 0; jc < nchunks; jc++) {
        const int col0 = jc * 64;
        const float* Uj = Ub + (long long)col0 * CC;
        const float* Vj = Vb + (long long)col0 * CC;
        // ---- load u chunk (64n x 64k) B-frag (TB): 4 float4/thread ----
#pragma unroll
        for (int i = 0; i < 4; i++) {
            int v = tid + i * 256;
            int n = v >> 4, c4 = v & 15;
            int ka = c4 >> 1, r = c4 & 1;
            int base = ((ka * 8 + (n >> 3)) * 32 + (n & 7) * 4) * 2 + r;
            float4 t = *reinterpret_cast<const float4*>(&Uj[(long long)n * CC + c4 * 4]);
            sU[base + 0 * 2] = f2tf32f(t.x);
            sU[base + 1 * 2] = f2tf32f(t.y);
            sU[base + 2 * 2] = f2tf32f(t.z);
            sU[base + 3 * 2] = f2tf32f(t.w);
        }
        // ---- load v chunk (64k x 64n) B-frag (NN): 4 float4/thread ----
#pragma unroll
        for (int i = 0; i < 4; i++) {
            int v = tid + i * 256;
            int krow = v >> 4;
            int nc = (v & 15) * 4;
            int ka = krow >> 3, kc = krow & 7;
            int r = kc >> 2, lc = kc & 3;
            int na = nc >> 3, nb = nc & 7;
            float4 t = *reinterpret_cast<const float4*>(&Vj[(long long)krow * CC + nc]);
            sV[((ka * 8 + na) * 32 + (nb + 0) * 4 + lc) * 2 + r] = f2tf32f(t.x);
            sV[((ka * 8 + na) * 32 + (nb + 1) * 4 + lc) * 2 + r] = f2tf32f(t.y);
            sV[((ka * 8 + na) * 32 + (nb + 2) * 4 + lc) * 2 + r] = f2tf32f(t.z);
            sV[((ka * 8 + na) * 32 + (nb + 3) * 4 + lc) * 2 + r] = f2tf32f(t.w);
        }
        __syncthreads();

        // Warp-level skip: chunk entirely above this warp's rows -> all P = 0.
        if (col0 <= rmaxw) {
            // ---- phase A: S = q @ u_chunk^T (8 ka x 8 na MMAs) ----
            float sAcc[8][4];
#pragma unroll
            for (int na = 0; na < 8; na++)
#pragma unroll
                for (int r = 0; r < 4; r++) sAcc[na][r] = 0.f;
#pragma unroll
            for (int ka = 0; ka < 8; ka++) {
                float4 aF = *reinterpret_cast<const float4*>(&sQ[((ka * 8 + w) * 32 + lane) * 4]);
#pragma unroll
                for (int na = 0; na < 8; na++) {
                    float2 bF = *reinterpret_cast<const float2*>(&sU[((ka * 8 + na) * 32 + lane) * 2]);
                    mma_tf32_16x8x8(sAcc[na], aF, bF);
                }
            }

            // ---- phase B: scale+bias, mask, chunk max, rescale ----
            const bool diag = (col0 + 63 > mt * 128);   // chunk reaches diagonal band
            float tm0 = -INFINITY, tm1 = -INFINITY;
#pragma unroll
            for (int na = 0; na < 8; na++) {
                int c0 = col0 + na * 8 + 2 * lq;
                float2 bb = *reinterpret_cast<const float2*>(&sBc[c0]);
                float s0 = sAcc[na][0] * 0.125f + bb.x;
                float s1 = sAcc[na][1] * 0.125f + bb.y;
                float s2 = sAcc[na][2] * 0.125f + bb.x;
                float s3 = sAcc[na][3] * 0.125f + bb.y;
                if (diag) {
                    if (c0 > r0g)         s0 = -1e30f;
                    if (c0 + 1 > r0g)     s1 = -1e30f;
                    if (c0 > r0g + 8)     s2 = -1e30f;
                    if (c0 + 1 > r0g + 8) s3 = -1e30f;
                }
                sAcc[na][0] = s0; sAcc[na][1] = s1; sAcc[na][2] = s2; sAcc[na][3] = s3;
                tm0 = fmaxf(tm0, fmaxf(s0, s1));
                tm1 = fmaxf(tm1, fmaxf(s2, s3));
            }
            tm0 = fmaxf(tm0, __shfl_xor_sync(0xffffffffu, tm0, 1));
            tm0 = fmaxf(tm0, __shfl_xor_sync(0xffffffffu, tm0, 2));
            tm1 = fmaxf(tm1, __shfl_xor_sync(0xffffffffu, tm1, 1));
            tm1 = fmaxf(tm1, __shfl_xor_sync(0xffffffffu, tm1, 2));

            const float nm0 = fmaxf(mrun0, tm0);
            const float nm1 = fmaxf(mrun1, tm1);
            const float sc0 = __expf(mrun0 - nm0);
            const float sc1 = __expf(mrun1 - nm1);
            mrun0 = nm0; mrun1 = nm1;
            lrun0 *= sc0; lrun1 *= sc1;
#pragma unroll
            for (int j = 0; j < 8; j++) {
                yacc[j][0] *= sc0; yacc[j][1] *= sc0;
                yacc[j][2] *= sc1; yacc[j][3] *= sc1;
            }

            // ---- phase B2+C per k-atom: exp -> shuffle-transpose -> 8 MMAs ----
            float ts0 = 0.f, ts1 = 0.f;
#pragma unroll
            for (int na = 0; na < 8; na++) {
                float p0 = __expf(sAcc[na][0] - nm0);
                float p1 = __expf(sAcc[na][1] - nm0);
                float p2 = __expf(sAcc[na][2] - nm1);
                float p3 = __expf(sAcc[na][3] - nm1);
                ts0 += p0 + p1;
                ts1 += p2 + p3;
                float e0A = __shfl_sync(0xffffffffu, p0, srcA);
                float e1A = __shfl_sync(0xffffffffu, p1, srcA);
                float e2A = __shfl_sync(0xffffffffu, p2, srcA);
                float e3A = __shfl_sync(0xffffffffu, p3, srcA);
                float e0B = __shfl_sync(0xffffffffu, p0, srcB);
                float e1B = __shfl_sync(0xffffffffu, p1, srcB);
                float e2B = __shfl_sync(0xffffffffu, p2, srcB);
                float e3B = __shfl_sync(0xffffffffu, p3, srcB);
                float4 aP;
                aP.x = f2tf32f(oddq ? e1A : e0A);   // (g, lq)
                aP.y = f2tf32f(oddq ? e3A : e2A);   // (g+8, lq)
                aP.z = f2tf32f(oddq ? e1B : e0B);   // (g, lq+4)
                aP.w = f2tf32f(oddq ? e3B : e2B);   // (g+8, lq+4)
#pragma unroll
                for (int j = 0; j < 8; j++) {
                    float2 bF = *reinterpret_cast<const float2*>(&sV[((na * 8 + j) * 32 + lane) * 2]);
                    mma_tf32_16x8x8(yacc[j], aP, bF);
                }
            }
            ts0 += __shfl_xor_sync(0xffffffffu, ts0, 1);
            ts0 += __shfl_xor_sync(0xffffffffu, ts0, 2);
            ts1 += __shfl_xor_sync(0xffffffffu, ts1, 1);
            ts1 += __shfl_xor_sync(0xffffffffu, ts1, 2);
            lrun0 += ts0; lrun1 += ts1;
        }
        __syncthreads();   // before next chunk overwrites sU/sV
    }

    // ---- epilogue: normalize, store ----
    const int row0 = mt * 128 + w * 16 + g;
    const float inv0 = 1.f / lrun0;
    const float inv1 = 1.f / lrun1;
#pragma unroll
    for (int j = 0; j < 8; j++) {
        int col = j * 8 + lq * 2;
        float2 t0 = make_float2(yacc[j][0] * inv0, yacc[j][1] * inv0);
        float2 t1 = make_float2(yacc[j][2] * inv1, yacc[j][3] * inv1);
        *reinterpret_cast<float2*>(&Cz[(long long)row0 * CC + col]) = t0;
        *reinterpret_cast<float2*>(&Cz[(long long)(row0 + 8) * CC + col]) = t1;
    }
}

// ---------------------------------------------------------------------------
extern "C" void kernel_launch(void* const* d_in, const int* in_sizes, int n_in,
                              void* d_out, int out_size)
{
    const float* x  = (const float*)d_in[0];
    const float* Wv = (const float*)d_in[1];
    const float* bv = (const float*)d_in[2];
    const float* Wl = (const float*)d_in[3];
    const float* Wc = (const float*)d_in[4];
    const float* bc = (const float*)d_in[5];
    const float* Wp = (const float*)d_in[6];
    const float* bp = (const float*)d_in[7];
    float* out = (float*)d_out;

    float *v_p, *u_p, *wcl_p, *y_p;
    cudaGetSymbolAddress((void**)&v_p,   g_v);
    cudaGetSymbolAddress((void**)&u_p,   g_u);
    cudaGetSymbolAddress((void**)&wcl_p, g_wcl);
    cudaGetSymbolAddress((void**)&y_p,   g_y);

    const long long sBTC = (long long)TT * CC;

    cudaFuncSetAttribute(flash_attn_k,
                         cudaFuncAttributeMaxDynamicSharedMemorySize,
                         FLASH_SMEM_BYTES);

    // 1) Wcl = Wc @ Wl   (tf32 NN)
    gemm_mma_k<128,2,4,false,false,false><<<dim3(8,8,1),256>>>(
        Wc, Wl, nullptr, wcl_p,
        TT, TT, TT, TT,
        0,0, 0,0, 0,0, 1, 1.0f);

    // 2) v = x @ Wv^T + bv   (tf32 NT)
    gemm_mma_k<128,2,4,true,false,false><<<dim3(CC/128, (BB*TT)/128, 1),256>>>(
        x, Wv, bv, v_p,
        CC, CC, CC, CC,
        0,0, 0,0, 0,0, 1, 1.0f);

    // 3) u[b] = Wcl @ v[b]   (tf32 NN, head-merged N=768)
    gemm_mma_k<128,2,4,false,false,false><<<dim3(CC/128, 8, BB),256>>>(
        wcl_p, v_p, nullptr, u_p,
        TT, TT, CC, CC,
        0,0, sBTC,0, sBTC,0, 1, 1.0f);

    // 4+5+6) y = softmax_causal(vh @ uh^T/8 + bc) @ vh   — fused flash
    flash_attn_k<<<dim3(8, BB*NHH), 256, FLASH_SMEM_BYTES>>>(
        v_p, u_p, bc, y_p);

    // 7) out = y @ Wp^T + bp   (tf32 NT)
    gemm_mma_k<128,2,4,true,false,false><<<dim3(CC/128, (BB*TT)/128, 1),256>>>(
        y_p, Wp, bp, out,
        CC, CC, CC, CC,
        0,0, 0,0, 0,0, 1, 1.0f);
}